// round 1
// baseline (speedup 1.0000x reference)
#include <cuda_runtime.h>
#include <cuda_bf16.h>
#include <math.h>

#define B_  32
#define N_  577
#define D_  384
#define L_  12
#define NR_ 4
#define H_  1536
#define KVMAX_ (N_ + NR_)      // 581 (>= 580 actually used)

static constexpr float LN_EPS = 1e-6f;
static constexpr float ATT_SCALE = 0.05103103630798288f; // 1/sqrt(384)

// ---------------------------------------------------------------------------
// Device scratch (static __device__ arrays — no allocation at runtime)
// ---------------------------------------------------------------------------
__device__ float g_x   [B_ * N_ * D_];
__device__ float g_xn  [B_ * N_ * D_];
__device__ float g_mem [B_ * KVMAX_ * D_];
__device__ float g_q   [B_ * N_ * D_];
__device__ float g_qln [B_ * N_ * D_];
__device__ float g_k   [B_ * KVMAX_ * D_];
__device__ float g_kln [B_ * KVMAX_ * D_];
__device__ float g_v   [B_ * KVMAX_ * D_];
__device__ float g_S   [B_ * N_ * KVMAX_];
__device__ float g_att [B_ * N_ * D_];
__device__ float g_aln [B_ * N_ * D_];
__device__ float g_h   [B_ * N_ * H_];
__device__ float g_hist[NR_ * B_ * D_];

// ---------------------------------------------------------------------------
// Assemble: x = [cls(prev), input[:,1:]], mem[:, :577] = x, hist[r] = cls
// prev may alias x (safe: only (b,0,d) thread touches x[b,0,d], value unchanged)
// ---------------------------------------------------------------------------
__global__ void assemble_kernel(const float* __restrict__ prev,
                                const float* __restrict__ xin,
                                float* __restrict__ x,
                                float* __restrict__ mem,
                                float* __restrict__ hist,
                                int r, int Mkv)
{
    long long idx = (long long)blockIdx.x * blockDim.x + threadIdx.x;
    if (idx >= (long long)B_ * N_ * D_) return;
    int d = (int)(idx % D_);
    long long bt = idx / D_;
    int t = (int)(bt % N_);
    int b = (int)(bt / N_);
    float v;
    if (t == 0) v = prev[((size_t)b * N_) * D_ + d];
    else        v = xin[idx];
    x[idx] = v;
    mem[((size_t)b * Mkv + t) * D_ + d] = v;
    if (t == 0) hist[((size_t)r * B_ + b) * D_ + d] = v;
}

__global__ void mem_tail_kernel(float* __restrict__ mem,
                                const float* __restrict__ hist,
                                int r, int Mkv)
{
    int idx = blockIdx.x * blockDim.x + threadIdx.x;
    if (idx >= B_ * r * D_) return;
    int d = idx % D_;
    int j = (idx / D_) % r;
    int b = idx / (D_ * r);
    mem[((size_t)b * Mkv + N_ + j) * D_ + d] = hist[((size_t)j * B_ + b) * D_ + d];
}

__global__ void copy_kernel(float* __restrict__ dst, const float* __restrict__ src, long long n)
{
    long long i = (long long)blockIdx.x * blockDim.x + threadIdx.x;
    if (i < n) dst[i] = src[i];
}

// ---------------------------------------------------------------------------
// LayerNorm over last dim (D=384). 1 block (128 thr) per row, 3 elems/thread.
// ---------------------------------------------------------------------------
__global__ __launch_bounds__(128) void ln_kernel(const float* __restrict__ in,
                                                 const float* __restrict__ w,
                                                 const float* __restrict__ bb,
                                                 float* __restrict__ out)
{
    const int row = blockIdx.x;
    const float* p = in + (size_t)row * D_;
    float* o = out + (size_t)row * D_;
    float v[3];
    float s = 0.f, sq = 0.f;
#pragma unroll
    for (int i = 0; i < 3; i++) {
        v[i] = p[threadIdx.x + i * 128];
        s += v[i];
        sq += v[i] * v[i];
    }
#pragma unroll
    for (int off = 16; off; off >>= 1) {
        s  += __shfl_xor_sync(0xffffffffu, s,  off);
        sq += __shfl_xor_sync(0xffffffffu, sq, off);
    }
    __shared__ float sh[8];
    const int wid = threadIdx.x >> 5;
    if ((threadIdx.x & 31) == 0) { sh[wid] = s; sh[4 + wid] = sq; }
    __syncthreads();
    s  = sh[0] + sh[1] + sh[2] + sh[3];
    sq = sh[4] + sh[5] + sh[6] + sh[7];
    const float mu  = s * (1.0f / D_);
    float var = sq * (1.0f / D_) - mu * mu;
    if (var < 0.f) var = 0.f;
    const float inv = rsqrtf(var + LN_EPS);
#pragma unroll
    for (int i = 0; i < 3; i++) {
        int c = threadIdx.x + i * 128;
        o[c] = (v[i] - mu) * inv * w[c] + bb[c];
    }
}

// ---------------------------------------------------------------------------
// Softmax in-place over rows of length `cols` (<= 640). 128 thr/row.
// ---------------------------------------------------------------------------
__global__ __launch_bounds__(128) void softmax_kernel(float* __restrict__ S, int cols)
{
    const int row = blockIdx.x;
    float* p = S + (size_t)row * cols;
    float v[5];
    float mx = -1e30f;
#pragma unroll
    for (int i = 0; i < 5; i++) {
        int c = threadIdx.x + i * 128;
        v[i] = (c < cols) ? p[c] : -1e30f;
        mx = fmaxf(mx, v[i]);
    }
#pragma unroll
    for (int off = 16; off; off >>= 1) mx = fmaxf(mx, __shfl_xor_sync(0xffffffffu, mx, off));
    __shared__ float shm[4];
    __shared__ float shs[4];
    const int wid = threadIdx.x >> 5;
    if ((threadIdx.x & 31) == 0) shm[wid] = mx;
    __syncthreads();
    mx = fmaxf(fmaxf(shm[0], shm[1]), fmaxf(shm[2], shm[3]));
    float s = 0.f;
#pragma unroll
    for (int i = 0; i < 5; i++) {
        v[i] = __expf(v[i] - mx);   // out-of-range lanes: exp(-huge) -> 0
        s += v[i];
    }
#pragma unroll
    for (int off = 16; off; off >>= 1) s += __shfl_xor_sync(0xffffffffu, s, off);
    if ((threadIdx.x & 31) == 0) shs[wid] = s;
    __syncthreads();
    s = shs[0] + shs[1] + shs[2] + shs[3];
    const float inv = 1.0f / s;
#pragma unroll
    for (int i = 0; i < 5; i++) {
        int c = threadIdx.x + i * 128;
        if (c < cols) p[c] = v[i] * inv;
    }
}

// ---------------------------------------------------------------------------
// SGEMM NT:  C[M,N] = scale * (A[M,K] @ B[N,K]^T) (+bias) (+epilogue)
// 128x128 tile, BK=8, 256 threads, 8x8 per thread (2x2 quadrants of 4x4).
// Batched via blockIdx.z with element strides sA/sB/sC. ld(A)=K, ld(B)=K, ld(C)=N.
// ---------------------------------------------------------------------------
enum { EPI_PLAIN = 0, EPI_GELU = 1, EPI_RESID = 2 };

template <int EPI>
__global__ __launch_bounds__(256) void gemm_nt(
    int M, int N, int K,
    const float* __restrict__ A,  long long sA,
    const float* __restrict__ Bw, long long sB,
    float* __restrict__ C,        long long sC,
    const float* __restrict__ bias,
    const float* __restrict__ ls,
    const float* __restrict__ res,
    float scale)
{
    __shared__ __align__(16) float As[8][128 + 4];
    __shared__ __align__(16) float Bs[8][128 + 4];

    const int bm = blockIdx.y * 128;
    const int bn = blockIdx.x * 128;
    const int z  = blockIdx.z;
    A  += (size_t)z * sA;
    Bw += (size_t)z * sB;
    C  += (size_t)z * sC;

    const int tid  = threadIdx.x;
    const int arow = tid >> 1;          // 0..127
    const int ac4  = (tid & 1) * 4;     // 0 or 4
    const int tx   = tid & 15;          // 0..15
    const int ty   = tid >> 4;          // 0..15

    float acc[8][8];
#pragma unroll
    for (int i = 0; i < 8; i++)
#pragma unroll
        for (int j = 0; j < 8; j++) acc[i][j] = 0.f;

    const bool aval = (bm + arow) < M;
    const bool bval = (bn + arow) < N;
    const float* Aptr = A  + (size_t)(bm + arow) * K;
    const float* Bptr = Bw + (size_t)(bn + arow) * K;

    for (int k0 = 0; k0 < K; k0 += 8) {
        float4 av = aval ? *(const float4*)(Aptr + k0 + ac4) : make_float4(0.f, 0.f, 0.f, 0.f);
        float4 bv = bval ? *(const float4*)(Bptr + k0 + ac4) : make_float4(0.f, 0.f, 0.f, 0.f);
        As[ac4 + 0][arow] = av.x; As[ac4 + 1][arow] = av.y;
        As[ac4 + 2][arow] = av.z; As[ac4 + 3][arow] = av.w;
        Bs[ac4 + 0][arow] = bv.x; Bs[ac4 + 1][arow] = bv.y;
        Bs[ac4 + 2][arow] = bv.z; Bs[ac4 + 3][arow] = bv.w;
        __syncthreads();
#pragma unroll
        for (int k = 0; k < 8; k++) {
            float ar[8], br[8];
            *(float4*)(ar)     = *(const float4*)&As[k][ty * 4];
            *(float4*)(ar + 4) = *(const float4*)&As[k][64 + ty * 4];
            *(float4*)(br)     = *(const float4*)&Bs[k][tx * 4];
            *(float4*)(br + 4) = *(const float4*)&Bs[k][64 + tx * 4];
#pragma unroll
            for (int i = 0; i < 8; i++)
#pragma unroll
                for (int j = 0; j < 8; j++) acc[i][j] += ar[i] * br[j];
        }
        __syncthreads();
    }

#pragma unroll
    for (int i = 0; i < 8; i++) {
        const int m = bm + ((i < 4) ? (ty * 4 + i) : (64 + ty * 4 + (i - 4)));
        if (m >= M) continue;
#pragma unroll
        for (int j = 0; j < 8; j++) {
            const int n = bn + ((j < 4) ? (tx * 4 + j) : (64 + tx * 4 + (j - 4)));
            if (n >= N) continue;
            float v = acc[i][j] * scale;
            if (bias) v += bias[n];
            if (EPI == EPI_GELU) {
                v = 0.5f * v * (1.0f + erff(v * 0.70710678118654752f));
            }
            if (EPI == EPI_RESID) {
                v = v * ls[n] + res[(size_t)m * N + n];
            }
            C[(size_t)m * N + n] = v;
        }
    }
}

// ---------------------------------------------------------------------------
// SGEMM NN:  C[M,N] = A[M,K] @ B[K,N]   (attn @ V). K not multiple of 8 -> guards.
// ld(A)=K, ld(B)=N, ld(C)=N. Batched via blockIdx.z.
// ---------------------------------------------------------------------------
__global__ __launch_bounds__(256) void gemm_nn(
    int M, int N, int K,
    const float* __restrict__ A,  long long sA,
    const float* __restrict__ Bm, long long sB,
    float* __restrict__ C,        long long sC)
{
    __shared__ __align__(16) float As[8][128 + 4];
    __shared__ __align__(16) float Bs[8][128 + 4];

    const int bm = blockIdx.y * 128;
    const int bn = blockIdx.x * 128;
    const int z  = blockIdx.z;
    A  += (size_t)z * sA;
    Bm += (size_t)z * sB;
    C  += (size_t)z * sC;

    const int tid  = threadIdx.x;
    const int arow = tid >> 1;
    const int ac4  = (tid & 1) * 4;
    const int krow = tid >> 5;            // 0..7
    const int nc4  = (tid & 31) * 4;      // 0..124
    const int tx   = tid & 15;
    const int ty   = tid >> 4;

    float acc[8][8];
#pragma unroll
    for (int i = 0; i < 8; i++)
#pragma unroll
        for (int j = 0; j < 8; j++) acc[i][j] = 0.f;

    const bool aval = (bm + arow) < M;
    const float* Aptr = A + (size_t)(bm + arow) * K;

    for (int k0 = 0; k0 < K; k0 += 8) {
        // A tile (transposed into smem), elementwise k-guards
#pragma unroll
        for (int i = 0; i < 4; i++) {
            int kk = k0 + ac4 + i;
            As[ac4 + i][arow] = (aval && kk < K) ? Aptr[kk] : 0.f;
        }
        // B tile (direct), float4 store per thread
        {
            int kk = k0 + krow;
            float4 bv = make_float4(0.f, 0.f, 0.f, 0.f);
            if (kk < K) {
                const float* bp = Bm + (size_t)kk * N + bn + nc4;
                if (bn + nc4 + 3 < N) {
                    bv = *(const float4*)bp;
                } else {
                    if (bn + nc4 + 0 < N) bv.x = bp[0];
                    if (bn + nc4 + 1 < N) bv.y = bp[1];
                    if (bn + nc4 + 2 < N) bv.z = bp[2];
                    if (bn + nc4 + 3 < N) bv.w = bp[3];
                }
            }
            *(float4*)&Bs[krow][nc4] = bv;
        }
        __syncthreads();
#pragma unroll
        for (int k = 0; k < 8; k++) {
            float ar[8], br[8];
            *(float4*)(ar)     = *(const float4*)&As[k][ty * 4];
            *(float4*)(ar + 4) = *(const float4*)&As[k][64 + ty * 4];
            *(float4*)(br)     = *(const float4*)&Bs[k][tx * 4];
            *(float4*)(br + 4) = *(const float4*)&Bs[k][64 + tx * 4];
#pragma unroll
            for (int i = 0; i < 8; i++)
#pragma unroll
                for (int j = 0; j < 8; j++) acc[i][j] += ar[i] * br[j];
        }
        __syncthreads();
    }

#pragma unroll
    for (int i = 0; i < 8; i++) {
        const int m = bm + ((i < 4) ? (ty * 4 + i) : (64 + ty * 4 + (i - 4)));
        if (m >= M) continue;
#pragma unroll
        for (int j = 0; j < 8; j++) {
            const int n = bn + ((j < 4) ? (tx * 4 + j) : (64 + tx * 4 + (j - 4)));
            if (n >= N) continue;
            C[(size_t)m * N + n] = acc[i][j];
        }
    }
}

// ---------------------------------------------------------------------------
// Host orchestration
// ---------------------------------------------------------------------------
static float* dev_ptr_of(const void* symbol)
{
    void* p = nullptr;
    cudaGetSymbolAddress(&p, symbol);
    return (float*)p;
}

extern "C" void kernel_launch(void* const* d_in, const int* in_sizes, int n_in,
                              void* d_out, int out_size)
{
    const float* xin     = (const float*)d_in[0];
    const float* norm1_w = (const float*)d_in[1];
    const float* norm1_b = (const float*)d_in[2];
    const float* qkv_w   = (const float*)d_in[3];
    const float* qkv_b   = (const float*)d_in[4];
    const float* qn_w    = (const float*)d_in[5];
    const float* qn_b    = (const float*)d_in[6];
    const float* kn_w    = (const float*)d_in[7];
    const float* kn_b    = (const float*)d_in[8];
    const float* an_w    = (const float*)d_in[9];
    const float* an_b    = (const float*)d_in[10];
    const float* proj_w  = (const float*)d_in[11];
    const float* proj_b  = (const float*)d_in[12];
    const float* ls1     = (const float*)d_in[13];
    const float* norm2_w = (const float*)d_in[14];
    const float* norm2_b = (const float*)d_in[15];
    const float* fc1_w   = (const float*)d_in[16];
    const float* fc1_b   = (const float*)d_in[17];
    const float* fc2_w   = (const float*)d_in[18];
    const float* fc2_b   = (const float*)d_in[19];
    const float* ls2     = (const float*)d_in[20];

    float* px    = dev_ptr_of(g_x);
    float* pxn   = dev_ptr_of(g_xn);
    float* pmem  = dev_ptr_of(g_mem);
    float* pq    = dev_ptr_of(g_q);
    float* pqln  = dev_ptr_of(g_qln);
    float* pk    = dev_ptr_of(g_k);
    float* pkln  = dev_ptr_of(g_kln);
    float* pv    = dev_ptr_of(g_v);
    float* pS    = dev_ptr_of(g_S);
    float* patt  = dev_ptr_of(g_att);
    float* paln  = dev_ptr_of(g_aln);
    float* ph    = dev_ptr_of(g_h);
    float* phist = dev_ptr_of(g_hist);

    const long long TOT = (long long)B_ * N_ * D_;
    const int Mq = B_ * N_;                 // 18464 rows of queries / x

    for (int r = 0; r < NR_; r++) {
        const int Mkv = N_ + r;
        const int Mk  = B_ * Mkv;

        assemble_kernel<<<(unsigned)((TOT + 255) / 256), 256>>>(
            (r == 0) ? xin : px, xin, px, pmem, phist, r, Mkv);
        if (r > 0) {
            int nt = B_ * r * D_;
            mem_tail_kernel<<<(nt + 255) / 256, 256>>>(pmem, phist, r, Mkv);
        }

        for (int l = 0; l < L_; l++) {
            const size_t wq  = (size_t)l * 3 * D_ * D_;
            const size_t wk  = wq + (size_t)D_ * D_;
            const size_t wv  = wk + (size_t)D_ * D_;
            const size_t bq  = (size_t)l * 3 * D_;

            // norm1
            ln_kernel<<<Mq, 128>>>(px, norm1_w + (size_t)l * D_, norm1_b + (size_t)l * D_, pxn);

            // q / k / v projections
            {
                dim3 g(3, (Mq + 127) / 128, 1);
                gemm_nt<EPI_PLAIN><<<g, 256>>>(Mq, D_, D_, pxn, 0, qkv_w + wq, 0, pq, 0,
                                               qkv_b + bq, nullptr, nullptr, 1.0f);
            }
            {
                dim3 g(3, (Mk + 127) / 128, 1);
                gemm_nt<EPI_PLAIN><<<g, 256>>>(Mk, D_, D_, pmem, 0, qkv_w + wk, 0, pk, 0,
                                               qkv_b + bq + D_, nullptr, nullptr, 1.0f);
                gemm_nt<EPI_PLAIN><<<g, 256>>>(Mk, D_, D_, pmem, 0, qkv_w + wv, 0, pv, 0,
                                               qkv_b + bq + 2 * D_, nullptr, nullptr, 1.0f);
            }

            // q / k LayerNorms
            ln_kernel<<<Mq, 128>>>(pq, qn_w + (size_t)l * D_, qn_b + (size_t)l * D_, pqln);
            ln_kernel<<<Mk, 128>>>(pk, kn_w + (size_t)l * D_, kn_b + (size_t)l * D_, pkln);

            // scores: S[b] = scale * (qln[b] @ kln[b]^T)   (batched over b)
            {
                dim3 g((Mkv + 127) / 128, (N_ + 127) / 128, B_);
                gemm_nt<EPI_PLAIN><<<g, 256>>>(N_, Mkv, D_,
                                               pqln, (long long)N_ * D_,
                                               pkln, (long long)Mkv * D_,
                                               pS,   (long long)N_ * Mkv,
                                               nullptr, nullptr, nullptr, ATT_SCALE);
            }

            softmax_kernel<<<B_ * N_, 128>>>(pS, Mkv);

            // attn @ V  (batched over b)
            {
                dim3 g(3, (N_ + 127) / 128, B_);
                gemm_nn<<<g, 256>>>(N_, D_, Mkv,
                                    pS,  (long long)N_ * Mkv,
                                    pv,  (long long)Mkv * D_,
                                    patt,(long long)N_ * D_);
            }

            // attn LN
            ln_kernel<<<Mq, 128>>>(patt, an_w + (size_t)l * D_, an_b + (size_t)l * D_, paln);

            // proj + ls1 * (.) + residual  (in-place into x)
            {
                dim3 g(3, (Mq + 127) / 128, 1);
                gemm_nt<EPI_RESID><<<g, 256>>>(Mq, D_, D_, paln, 0,
                                               proj_w + (size_t)l * D_ * D_, 0, px, 0,
                                               proj_b + (size_t)l * D_,
                                               ls1 + (size_t)l * D_, px, 1.0f);
            }

            // norm2
            ln_kernel<<<Mq, 128>>>(px, norm2_w + (size_t)l * D_, norm2_b + (size_t)l * D_, pxn);

            // fc1 + exact GELU
            {
                dim3 g(12, (Mq + 127) / 128, 1);
                gemm_nt<EPI_GELU><<<g, 256>>>(Mq, H_, D_, pxn, 0,
                                              fc1_w + (size_t)l * H_ * D_, 0, ph, 0,
                                              fc1_b + (size_t)l * H_, nullptr, nullptr, 1.0f);
            }

            // fc2 + ls2 * (.) + residual
            {
                dim3 g(3, (Mq + 127) / 128, 1);
                gemm_nt<EPI_RESID><<<g, 256>>>(Mq, D_, H_, ph, 0,
                                               fc2_w + (size_t)l * D_ * H_, 0, px, 0,
                                               fc2_b + (size_t)l * D_,
                                               ls2 + (size_t)l * D_, px, 1.0f);
            }
        }
    }

    copy_kernel<<<(unsigned)((TOT + 255) / 256), 256>>>((float*)d_out, px, TOT);
}

// round 7
// speedup vs baseline: 1.3830x; 1.3830x over previous
#include <cuda_runtime.h>
#include <cuda_bf16.h>
#include <math.h>
#include <stdint.h>

#define B_  32
#define N_  577
#define D_  384
#define L_  12
#define NR_ 4
#define H_  1536
#define KVMAX_ (N_ + NR_)

static constexpr float LN_EPS = 1e-6f;
static constexpr float ATT_SCALE = 0.05103103630798288f; // 1/sqrt(384)

// ---------------------------------------------------------------------------
// Device scratch
// ---------------------------------------------------------------------------
__device__ float g_x   [B_ * N_ * D_];
__device__ float g_xn  [B_ * N_ * D_];
__device__ float g_mem [B_ * KVMAX_ * D_];
__device__ float g_q   [B_ * N_ * D_];
__device__ float g_qln [B_ * N_ * D_];
__device__ float g_k   [B_ * KVMAX_ * D_];
__device__ float g_kln [B_ * KVMAX_ * D_];
__device__ float g_v   [B_ * KVMAX_ * D_];
__device__ float g_S   [B_ * N_ * KVMAX_];
__device__ float g_att [B_ * N_ * D_];
__device__ float g_aln [B_ * N_ * D_];
__device__ float g_h   [B_ * N_ * H_];
__device__ float g_hist[NR_ * B_ * D_];

// ---------------------------------------------------------------------------
// Small kernels (assemble / copy / LN / softmax)
// ---------------------------------------------------------------------------
__global__ void assemble_kernel(const float* __restrict__ prev,
                                const float* __restrict__ xin,
                                float* __restrict__ x,
                                float* __restrict__ mem,
                                float* __restrict__ hist,
                                int r, int Mkv)
{
    long long idx = (long long)blockIdx.x * blockDim.x + threadIdx.x;
    if (idx >= (long long)B_ * N_ * D_) return;
    int d = (int)(idx % D_);
    long long bt = idx / D_;
    int t = (int)(bt % N_);
    int b = (int)(bt / N_);
    float v;
    if (t == 0) v = prev[((size_t)b * N_) * D_ + d];
    else        v = xin[idx];
    x[idx] = v;
    mem[((size_t)b * Mkv + t) * D_ + d] = v;
    if (t == 0) hist[((size_t)r * B_ + b) * D_ + d] = v;
}

__global__ void mem_tail_kernel(float* __restrict__ mem,
                                const float* __restrict__ hist,
                                int r, int Mkv)
{
    int idx = blockIdx.x * blockDim.x + threadIdx.x;
    if (idx >= B_ * r * D_) return;
    int d = idx % D_;
    int j = (idx / D_) % r;
    int b = idx / (D_ * r);
    mem[((size_t)b * Mkv + N_ + j) * D_ + d] = hist[((size_t)j * B_ + b) * D_ + d];
}

__global__ void copy_kernel(float* __restrict__ dst, const float* __restrict__ src, long long n)
{
    long long i = (long long)blockIdx.x * blockDim.x + threadIdx.x;
    if (i < n) dst[i] = src[i];
}

__global__ __launch_bounds__(128) void ln_kernel(const float* __restrict__ in,
                                                 const float* __restrict__ w,
                                                 const float* __restrict__ bb,
                                                 float* __restrict__ out)
{
    const int row = blockIdx.x;
    const float* p = in + (size_t)row * D_;
    float* o = out + (size_t)row * D_;
    float v[3];
    float s = 0.f, sq = 0.f;
#pragma unroll
    for (int i = 0; i < 3; i++) {
        v[i] = p[threadIdx.x + i * 128];
        s += v[i];
        sq += v[i] * v[i];
    }
#pragma unroll
    for (int off = 16; off; off >>= 1) {
        s  += __shfl_xor_sync(0xffffffffu, s,  off);
        sq += __shfl_xor_sync(0xffffffffu, sq, off);
    }
    __shared__ float sh[8];
    const int wid = threadIdx.x >> 5;
    if ((threadIdx.x & 31) == 0) { sh[wid] = s; sh[4 + wid] = sq; }
    __syncthreads();
    s  = sh[0] + sh[1] + sh[2] + sh[3];
    sq = sh[4] + sh[5] + sh[6] + sh[7];
    const float mu  = s * (1.0f / D_);
    float var = sq * (1.0f / D_) - mu * mu;
    if (var < 0.f) var = 0.f;
    const float inv = rsqrtf(var + LN_EPS);
#pragma unroll
    for (int i = 0; i < 3; i++) {
        int c = threadIdx.x + i * 128;
        o[c] = (v[i] - mu) * inv * w[c] + bb[c];
    }
}

__global__ __launch_bounds__(128) void softmax_kernel(float* __restrict__ S, int cols)
{
    const int row = blockIdx.x;
    float* p = S + (size_t)row * cols;
    float v[5];
    float mx = -1e30f;
#pragma unroll
    for (int i = 0; i < 5; i++) {
        int c = threadIdx.x + i * 128;
        v[i] = (c < cols) ? p[c] : -1e30f;
        mx = fmaxf(mx, v[i]);
    }
#pragma unroll
    for (int off = 16; off; off >>= 1) mx = fmaxf(mx, __shfl_xor_sync(0xffffffffu, mx, off));
    __shared__ float shm[4];
    __shared__ float shs[4];
    const int wid = threadIdx.x >> 5;
    if ((threadIdx.x & 31) == 0) shm[wid] = mx;
    __syncthreads();
    mx = fmaxf(fmaxf(shm[0], shm[1]), fmaxf(shm[2], shm[3]));
    float s = 0.f;
#pragma unroll
    for (int i = 0; i < 5; i++) {
        v[i] = __expf(v[i] - mx);
        s += v[i];
    }
#pragma unroll
    for (int off = 16; off; off >>= 1) s += __shfl_xor_sync(0xffffffffu, s, off);
    if ((threadIdx.x & 31) == 0) shs[wid] = s;
    __syncthreads();
    s = shs[0] + shs[1] + shs[2] + shs[3];
    const float inv = 1.0f / s;
#pragma unroll
    for (int i = 0; i < 5; i++) {
        int c = threadIdx.x + i * 128;
        if (c < cols) p[c] = v[i] * inv;
    }
}

// ---------------------------------------------------------------------------
// bf16-split tensor-core GEMM.
//   MODE 0 (NT): C[M,Nb] = scale*(A[M,K] @ B[Nb,K]^T), K % 32 == 0
//   MODE 1 (NN): C[M,Nb] = A[M,K] @ B[K,Nb]            (arbitrary K)
// Split: x = hi(x) + lo(x) in bf16; acc += Ah*Bh + Al*Bh + Ah*Bl (fp32 acc).
// Block 128x128, BK=32, 256 threads, warp tile 64x32 (2x4 warps).
// Smem layout: per row, k-pair p stored as interleaved (hi,lo) uint32 words at
// word index (2p) ^ ((row&3)<<3)  -> conflict-free 64-bit fragment loads.
// ---------------------------------------------------------------------------
#define BM 128
#define BN 128
#define BK 32
#define SROW 32     // uint32 words per smem row

enum { EPI_PLAIN = 0, EPI_GELU = 1, EPI_RESID = 2 };

__device__ __forceinline__ uint32_t pack2u(__nv_bfloat16 a, __nv_bfloat16 b)
{
    return (uint32_t)__bfloat16_as_ushort(a) | ((uint32_t)__bfloat16_as_ushort(b) << 16);
}

__device__ __forceinline__ void split2(float x, __nv_bfloat16& h, __nv_bfloat16& l)
{
    h = __float2bfloat16_rn(x);
    l = __float2bfloat16_rn(x - __bfloat162float(h));
}

__device__ __forceinline__ void mma16816(float* d,
                                         uint32_t a0, uint32_t a1, uint32_t a2, uint32_t a3,
                                         uint32_t b0, uint32_t b1)
{
    asm volatile(
        "mma.sync.aligned.m16n8k16.row.col.f32.bf16.bf16.f32 "
        "{%0,%1,%2,%3}, {%4,%5,%6,%7}, {%8,%9}, {%0,%1,%2,%3};\n"
        : "+f"(d[0]), "+f"(d[1]), "+f"(d[2]), "+f"(d[3])
        : "r"(a0), "r"(a1), "r"(a2), "r"(a3), "r"(b0), "r"(b1));
}

// K-major tile load into regs (16 floats / thread). VEC: K%32==0 & aligned.
template <bool VEC>
__device__ __forceinline__ void load_km_regs(float* r, const float* Gm, int rows,
                                             int K, int rbase, int k0, int tid)
{
    const int lrow = tid >> 1;
    const int lk   = (tid & 1) << 4;
    const bool rv  = (rbase + lrow) < rows;
    const float* p = Gm + (size_t)(rbase + lrow) * K + k0 + lk;
    if (VEC) {
        if (rv) {
#pragma unroll
            for (int j = 0; j < 4; j++) ((float4*)r)[j] = ((const float4*)p)[j];
        } else {
#pragma unroll
            for (int j = 0; j < 16; j++) r[j] = 0.f;
        }
    } else {
#pragma unroll
        for (int j = 0; j < 16; j++)
            r[j] = (rv && (k0 + lk + j) < K) ? p[j] : 0.f;
    }
}

// store K-major staged regs into swizzled smem
__device__ __forceinline__ void store_km_smem(uint32_t* S, const float* r, int tid)
{
    const int lrow = tid >> 1;
    const int lk   = (tid & 1) << 4;
    uint32_t* dst = S + lrow * SROW;
    const int xr = (lrow & 3) << 3;
#pragma unroll
    for (int j = 0; j < 4; j++) {
        __nv_bfloat16 h0, l0, h1, l1, h2, l2, h3, l3;
        split2(r[4 * j + 0], h0, l0);
        split2(r[4 * j + 1], h1, l1);
        split2(r[4 * j + 2], h2, l2);
        split2(r[4 * j + 3], h3, l3);
        uint4 w;
        w.x = pack2u(h0, h1);
        w.y = pack2u(l0, l1);
        w.z = pack2u(h2, h3);
        w.w = pack2u(l2, l3);
        *(uint4*)(dst + ((lk + 4 * j) ^ xr)) = w;
    }
}

// NN B tile: gmem [K][ldB] rows k0..k0+31, cols bn..bn+127 -> regs
__device__ __forceinline__ void load_nn_b_regs(float* r, const float* Bm, int K, int ldB,
                                               int bn, int k0, int tid)
{
    const int lk = tid & 31;
    const int nb = (tid >> 5) << 4;
    const bool kv = (k0 + lk) < K;
    const float* p = Bm + (size_t)(k0 + lk) * ldB + bn + nb;
#pragma unroll
    for (int j = 0; j < 4; j++) {
        float4 v = kv ? ((const float4*)p)[j] : make_float4(0.f, 0.f, 0.f, 0.f);
        r[4 * j + 0] = v.x; r[4 * j + 1] = v.y; r[4 * j + 2] = v.z; r[4 * j + 3] = v.w;
    }
}

__device__ __forceinline__ void store_nn_b_smem(uint32_t* S, const float* r, int tid)
{
    const int lk = tid & 31;
    const int nb = (tid >> 5) << 4;
    __nv_bfloat16* sb = (__nv_bfloat16*)S;
    const int kp2  = (lk >> 1) * 2;
    const int half = lk & 1;
#pragma unroll
    for (int j = 0; j < 16; j++) {
        const int n = nb + j;
        __nv_bfloat16 h, l;
        split2(r[j], h, l);
        const int w0 = kp2 ^ ((n & 3) << 3);
        sb[(n * SROW + w0) * 2 + half]     = h;
        sb[(n * SROW + w0 + 1) * 2 + half] = l;
    }
}

template <int MODE, int EPI>
__global__ __launch_bounds__(256, 1) void gemm_tc(
    int M, int Nb, int K,
    const float* __restrict__ A,  long long sA,
    const float* __restrict__ Bm, long long sB,
    float* __restrict__ C,        long long sC,
    const float* __restrict__ bias,
    const float* __restrict__ ls,
    const float* __restrict__ res,
    float scale)
{
    __shared__ __align__(16) uint32_t As[BM * SROW];
    __shared__ __align__(16) uint32_t Bs[BN * SROW];

    const int bm = blockIdx.y * BM;
    const int bn = blockIdx.x * BN;
    const int z  = blockIdx.z;
    A  += (size_t)z * sA;
    Bm += (size_t)z * sB;
    C  += (size_t)z * sC;

    const int tid  = threadIdx.x;
    const int lane = tid & 31;
    const int wid  = tid >> 5;
    const int g    = lane >> 2;
    const int t0   = lane & 3;
    const int wm   = (wid >> 2) * 64;   // warp M offset (0/64)
    const int wn   = (wid & 3) * 32;    // warp N offset (0/32/64/96)

    float acc[4][4][4];
#pragma unroll
    for (int i = 0; i < 4; i++)
#pragma unroll
        for (int j = 0; j < 4; j++)
#pragma unroll
            for (int c = 0; c < 4; c++) acc[i][j][c] = 0.f;

    float ar[16], br[16];
    // prologue loads
    if (MODE == 0) {
        load_km_regs<true>(ar, A, M, K, bm, 0, tid);
        load_km_regs<true>(br, Bm, Nb, K, bn, 0, tid);
    } else {
        load_km_regs<false>(ar, A, M, K, bm, 0, tid);
        load_nn_b_regs(br, Bm, K, Nb, bn, 0, tid);
    }

    for (int k0 = 0; k0 < K; k0 += BK) {
        store_km_smem(As, ar, tid);
        if (MODE == 0) store_km_smem(Bs, br, tid);
        else           store_nn_b_smem(Bs, br, tid);
        __syncthreads();

        if (k0 + BK < K) {
            if (MODE == 0) {
                load_km_regs<true>(ar, A, M, K, bm, k0 + BK, tid);
                load_km_regs<true>(br, Bm, Nb, K, bn, k0 + BK, tid);
            } else {
                load_km_regs<false>(ar, A, M, K, bm, k0 + BK, tid);
                load_nn_b_regs(br, Bm, K, Nb, bn, k0 + BK, tid);
            }
        }

#pragma unroll
        for (int ks = 0; ks < 2; ks++) {
            const int kpa = ks * 8 + t0;
            uint2 Bq[4][2];
#pragma unroll
            for (int na = 0; na < 4; na++) {
                const int brow = wn + na * 8 + g;
                const uint32_t* bb2 = Bs + brow * SROW;
                const int xr = (brow & 3) << 3;
                Bq[na][0] = *(const uint2*)(bb2 + ((kpa * 2) ^ xr));
                Bq[na][1] = *(const uint2*)(bb2 + (((kpa + 4) * 2) ^ xr));
            }
#pragma unroll
            for (int ma = 0; ma < 4; ma++) {
                const int ar0 = wm + ma * 16 + g;
                const int ar1 = ar0 + 8;
                const int xr = (ar0 & 3) << 3;
                const int w0 = (kpa * 2) ^ xr;
                const int w1 = ((kpa + 4) * 2) ^ xr;
                uint2 q0 = *(const uint2*)(As + ar0 * SROW + w0);
                uint2 q1 = *(const uint2*)(As + ar1 * SROW + w0);
                uint2 q2 = *(const uint2*)(As + ar0 * SROW + w1);
                uint2 q3 = *(const uint2*)(As + ar1 * SROW + w1);
#pragma unroll
                for (int na = 0; na < 4; na++) {
                    float* d = acc[ma][na];
                    mma16816(d, q0.x, q1.x, q2.x, q3.x, Bq[na][0].x, Bq[na][1].x); // Ah*Bh
                    mma16816(d, q0.y, q1.y, q2.y, q3.y, Bq[na][0].x, Bq[na][1].x); // Al*Bh
                    mma16816(d, q0.x, q1.x, q2.x, q3.x, Bq[na][0].y, Bq[na][1].y); // Ah*Bl
                }
            }
        }
        __syncthreads();
    }

    // epilogue
#pragma unroll
    for (int ma = 0; ma < 4; ma++) {
        const int m0 = bm + wm + ma * 16 + g;
#pragma unroll
        for (int na = 0; na < 4; na++) {
            const int nc = bn + wn + na * 8 + t0 * 2;
            const float* d = acc[ma][na];
#pragma unroll
            for (int c = 0; c < 4; c++) {
                const int m = m0 + (c >> 1) * 8;
                const int n = nc + (c & 1);
                if (m >= M || n >= Nb) continue;
                float v = d[c] * scale;
                if (bias) v += bias[n];
                if (EPI == EPI_GELU)  v = 0.5f * v * (1.0f + erff(v * 0.70710678118654752f));
                if (EPI == EPI_RESID) v = v * ls[n] + res[(size_t)m * Nb + n];
                C[(size_t)m * Nb + n] = v;
            }
        }
    }
}

// ---------------------------------------------------------------------------
// Host orchestration
// ---------------------------------------------------------------------------
static float* dev_ptr_of(const void* symbol)
{
    void* p = nullptr;
    cudaGetSymbolAddress(&p, symbol);
    return (float*)p;
}

extern "C" void kernel_launch(void* const* d_in, const int* in_sizes, int n_in,
                              void* d_out, int out_size)
{
    const float* xin     = (const float*)d_in[0];
    const float* norm1_w = (const float*)d_in[1];
    const float* norm1_b = (const float*)d_in[2];
    const float* qkv_w   = (const float*)d_in[3];
    const float* qkv_b   = (const float*)d_in[4];
    const float* qn_w    = (const float*)d_in[5];
    const float* qn_b    = (const float*)d_in[6];
    const float* kn_w    = (const float*)d_in[7];
    const float* kn_b    = (const float*)d_in[8];
    const float* an_w    = (const float*)d_in[9];
    const float* an_b    = (const float*)d_in[10];
    const float* proj_w  = (const float*)d_in[11];
    const float* proj_b  = (const float*)d_in[12];
    const float* ls1     = (const float*)d_in[13];
    const float* norm2_w = (const float*)d_in[14];
    const float* norm2_b = (const float*)d_in[15];
    const float* fc1_w   = (const float*)d_in[16];
    const float* fc1_b   = (const float*)d_in[17];
    const float* fc2_w   = (const float*)d_in[18];
    const float* fc2_b   = (const float*)d_in[19];
    const float* ls2     = (const float*)d_in[20];

    float* px    = dev_ptr_of(g_x);
    float* pxn   = dev_ptr_of(g_xn);
    float* pmem  = dev_ptr_of(g_mem);
    float* pq    = dev_ptr_of(g_q);
    float* pqln  = dev_ptr_of(g_qln);
    float* pk    = dev_ptr_of(g_k);
    float* pkln  = dev_ptr_of(g_kln);
    float* pv    = dev_ptr_of(g_v);
    float* pS    = dev_ptr_of(g_S);
    float* patt  = dev_ptr_of(g_att);
    float* paln  = dev_ptr_of(g_aln);
    float* ph    = dev_ptr_of(g_h);
    float* phist = dev_ptr_of(g_hist);

    const long long TOT = (long long)B_ * N_ * D_;
    const int Mq = B_ * N_;

    for (int r = 0; r < NR_; r++) {
        const int Mkv = N_ + r;
        const int Mk  = B_ * Mkv;

        assemble_kernel<<<(unsigned)((TOT + 255) / 256), 256>>>(
            (r == 0) ? xin : px, xin, px, pmem, phist, r, Mkv);
        if (r > 0) {
            int nt = B_ * r * D_;
            mem_tail_kernel<<<(nt + 255) / 256, 256>>>(pmem, phist, r, Mkv);
        }

        for (int l = 0; l < L_; l++) {
            const size_t wq = (size_t)l * 3 * D_ * D_;
            const size_t wk = wq + (size_t)D_ * D_;
            const size_t wv = wk + (size_t)D_ * D_;
            const size_t bq = (size_t)l * 3 * D_;

            ln_kernel<<<Mq, 128>>>(px, norm1_w + (size_t)l * D_, norm1_b + (size_t)l * D_, pxn);

            {
                dim3 g(3, (Mq + BM - 1) / BM, 1);
                gemm_tc<0, EPI_PLAIN><<<g, 256>>>(Mq, D_, D_, pxn, 0, qkv_w + wq, 0, pq, 0,
                                                  qkv_b + bq, nullptr, nullptr, 1.0f);
            }
            {
                dim3 g(3, (Mk + BM - 1) / BM, 1);
                gemm_tc<0, EPI_PLAIN><<<g, 256>>>(Mk, D_, D_, pmem, 0, qkv_w + wk, 0, pk, 0,
                                                  qkv_b + bq + D_, nullptr, nullptr, 1.0f);
                gemm_tc<0, EPI_PLAIN><<<g, 256>>>(Mk, D_, D_, pmem, 0, qkv_w + wv, 0, pv, 0,
                                                  qkv_b + bq + 2 * D_, nullptr, nullptr, 1.0f);
            }

            ln_kernel<<<Mq, 128>>>(pq, qn_w + (size_t)l * D_, qn_b + (size_t)l * D_, pqln);
            ln_kernel<<<Mk, 128>>>(pk, kn_w + (size_t)l * D_, kn_b + (size_t)l * D_, pkln);

            // scores: S[b] = scale * qln[b] @ kln[b]^T
            {
                dim3 g((Mkv + BN - 1) / BN, (N_ + BM - 1) / BM, B_);
                gemm_tc<0, EPI_PLAIN><<<g, 256>>>(N_, Mkv, D_,
                                                  pqln, (long long)N_ * D_,
                                                  pkln, (long long)Mkv * D_,
                                                  pS,   (long long)N_ * Mkv,
                                                  nullptr, nullptr, nullptr, ATT_SCALE);
            }

            softmax_kernel<<<B_ * N_, 128>>>(pS, Mkv);

            // attn @ V
            {
                dim3 g(3, (N_ + BM - 1) / BM, B_);
                gemm_tc<1, EPI_PLAIN><<<g, 256>>>(N_, D_, Mkv,
                                                  pS,  (long long)N_ * Mkv,
                                                  pv,  (long long)Mkv * D_,
                                                  patt,(long long)N_ * D_,
                                                  nullptr, nullptr, nullptr, 1.0f);
            }

            ln_kernel<<<Mq, 128>>>(patt, an_w + (size_t)l * D_, an_b + (size_t)l * D_, paln);

            {
                dim3 g(3, (Mq + BM - 1) / BM, 1);
                gemm_tc<0, EPI_RESID><<<g, 256>>>(Mq, D_, D_, paln, 0,
                                                  proj_w + (size_t)l * D_ * D_, 0, px, 0,
                                                  proj_b + (size_t)l * D_,
                                                  ls1 + (size_t)l * D_, px, 1.0f);
            }

            ln_kernel<<<Mq, 128>>>(px, norm2_w + (size_t)l * D_, norm2_b + (size_t)l * D_, pxn);

            {
                dim3 g(12, (Mq + BM - 1) / BM, 1);
                gemm_tc<0, EPI_GELU><<<g, 256>>>(Mq, H_, D_, pxn, 0,
                                                 fc1_w + (size_t)l * H_ * D_, 0, ph, 0,
                                                 fc1_b + (size_t)l * H_, nullptr, nullptr, 1.0f);
            }

            {
                dim3 g(3, (Mq + BM - 1) / BM, 1);
                gemm_tc<0, EPI_RESID><<<g, 256>>>(Mq, D_, H_, ph, 0,
                                                  fc2_w + (size_t)l * D_ * H_, 0, px, 0,
                                                  fc2_b + (size_t)l * D_,
                                                  ls2 + (size_t)l * D_, px, 1.0f);
            }
        }
    }

    copy_kernel<<<(unsigned)((TOT + 255) / 256), 256>>>((float*)d_out, px, TOT);
}